// round 11
// baseline (speedup 1.0000x reference)
#include <cuda_runtime.h>
#include <cuda_fp16.h>
#include <stdint.h>

#define DD 512
#define HH 1024
#define NTOK 4096
#define SS 2
#define GG 2
#define NGR 6
#define CC 32
#define KK 3
#define NEVT 50
#define BM 128
#define BN 128
#define BK 32
#define MAXTILES 40
#define NBANK (SS + NGR * GG)
#define NSHT (NTOK / BM)       // 32 shared tiles
#define LDHB 80                // bytes per smem row (32 halfs + 8 pad)
#define ARRB 10240             // bytes per array per stage (128*80)
#define STAGEB (4 * ARRB)      // 40960
#define NSTAGE 4
#define SMEM_TOT (NSTAGE * STAGEB)

// ---------------- device scratch (no cudaMalloc; 16B-aligned for vector ops) --
__device__ __align__(16) __half gx_hi[NTOK * DD], gx_lo[NTOK * DD];
__device__ __align__(16) __half gw1_hi[NBANK * HH * DD], gw1_lo[NBANK * HH * DD]; // [bank][N][K]
__device__ __align__(16) __half gw2_hi[NBANK * DD * HH], gw2_lo[NBANK * DD * HH];
__device__ __align__(16) __half gh1s_hi[NTOK * SS * HH], gh1s_lo[NTOK * SS * HH];
__device__ __align__(16) __half gh1g_hi[NTOK * GG * HH], gh1g_lo[NTOK * GG * HH];
__device__ __align__(16) float g_outs[NTOK * SS * DD], g_outg[NTOK * GG * DD];
__device__ int g_gid[NTOK], g_perm[NTOK];
__device__ int g_tile_group[MAXTILES], g_tile_m0[MAXTILES], g_tile_end[MAXTILES], g_ntiles;

// ---------------- PTX helpers ------------------------------------------------
__device__ __forceinline__ void cp16(uint32_t d, const void* s, bool v) {
    int sz = v ? 16 : 0;
    asm volatile("cp.async.cg.shared.global [%0], [%1], 16, %2;" :: "r"(d), "l"(s), "r"(sz));
}
#define CPC() asm volatile("cp.async.commit_group;")
#define CPW(N) asm volatile("cp.async.wait_group %0;" :: "n"(N))
#define LDSM4(r, a) asm volatile("ldmatrix.sync.aligned.m8n8.x4.shared.b16 {%0,%1,%2,%3}, [%4];" \
    : "=r"((r)[0]), "=r"((r)[1]), "=r"((r)[2]), "=r"((r)[3]) : "r"(a))
#define MMA16(d, a, b) asm volatile( \
    "mma.sync.aligned.m16n8k16.row.col.f32.f16.f16.f32 " \
    "{%0,%1,%2,%3}, {%4,%5,%6,%7}, {%8,%9}, {%0,%1,%2,%3};" \
    : "+f"((d)[0]), "+f"((d)[1]), "+f"((d)[2]), "+f"((d)[3]) \
    : "r"((a)[0]), "r"((a)[1]), "r"((a)[2]), "r"((a)[3]), "r"((b)[0]), "r"((b)[1]))

// ---------------- prep: group ids + counting sort + tile table --------------
__global__ void k_prep(const int* __restrict__ nti, const int* __restrict__ e2g) {
    __shared__ int cnt[NGR], st[NGR], cur[NGR];
    int t = threadIdx.x;
    if (t < NGR) cnt[t] = 0;
    __syncthreads();
    for (int n = t; n < NTOK; n += blockDim.x) {
        int v = nti[n]; v = v < 0 ? 0 : (v > NEVT - 1 ? NEVT - 1 : v);
        int g = e2g[v]; g_gid[n] = g; atomicAdd(&cnt[g], 1);
    }
    __syncthreads();
    if (t == 0) {
        int acc = 0, ntl = 0;
        for (int g = 0; g < NGR; g++) {
            st[g] = acc; int c = cnt[g];
            for (int m0 = acc; m0 < acc + c; m0 += BM) {
                g_tile_group[ntl] = g; g_tile_m0[ntl] = m0; g_tile_end[ntl] = acc + c; ntl++;
            }
            acc += c;
        }
        g_ntiles = ntl;
        for (int g = 0; g < NGR; g++) cur[g] = st[g];
    }
    __syncthreads();
    for (int n = t; n < NTOK; n += blockDim.x) {
        int pos = atomicAdd(&cur[g_gid[n]], 1);
        g_perm[pos] = n;
    }
}

// ---------------- split x -> fp16 hi/lo (vectorized) -------------------------
__global__ void k_cvt_x(const float4* __restrict__ x) {
    int i = blockIdx.x * 256 + threadIdx.x;
    float4 v = x[i];
    __half h0 = __float2half_rn(v.x), h1 = __float2half_rn(v.y);
    __half h2 = __float2half_rn(v.z), h3 = __float2half_rn(v.w);
    __half2 H0; H0.x = h0; H0.y = h1;
    __half2 H1; H1.x = h2; H1.y = h3;
    __half2 L0, L1;
    L0.x = __float2half_rn(v.x - __half2float(h0));
    L0.y = __float2half_rn(v.y - __half2float(h1));
    L1.x = __float2half_rn(v.z - __half2float(h2));
    L1.y = __float2half_rn(v.w - __half2float(h3));
    reinterpret_cast<__half2*>(gx_hi)[2 * i] = H0;
    reinterpret_cast<__half2*>(gx_hi)[2 * i + 1] = H1;
    reinterpret_cast<__half2*>(gx_lo)[2 * i] = L0;
    reinterpret_cast<__half2*>(gx_lo)[2 * i + 1] = L1;
}

// src [nb][Kd][Nd] fp32 -> dst [bank0+b][Nd][Kd] fp16 hi/lo (transposed, coalesced)
__global__ void k_cvt_w(const float* __restrict__ src, int Kd, int Nd, int which, int bank0) {
    __shared__ float s[64][33];
    int b = blockIdx.z, k0 = blockIdx.x * 64, n0 = blockIdx.y * 32;
    const float* sp = src + (size_t)b * Kd * Nd;
    int tx = threadIdx.x, ty = threadIdx.y;   // (32, 8)
    for (int r = ty; r < 64; r += 8)
        s[r][tx] = sp[(size_t)(k0 + r) * Nd + n0 + tx];
    __syncthreads();
    __half2* dh = reinterpret_cast<__half2*>(which ? gw2_hi : gw1_hi);
    __half2* dl = reinterpret_cast<__half2*>(which ? gw2_lo : gw1_lo);
    for (int nl = ty; nl < 32; nl += 8) {
        float v0 = s[2 * tx][nl], v1 = s[2 * tx + 1][nl];
        __half h0 = __float2half_rn(v0), h1 = __float2half_rn(v1);
        __half2 H; H.x = h0; H.y = h1;
        __half2 L;
        L.x = __float2half_rn(v0 - __half2float(h0));
        L.y = __float2half_rn(v1 - __half2float(h1));
        size_t o = (((size_t)(bank0 + b) * Nd + n0 + nl) * Kd + k0) / 2 + tx;
        dh[o] = H;
        dl[o] = L;
    }
}

// ---------------- fp16x3 tensor GEMM, merged shared+grouped per layer --------
// LAYER 1: h1 = relu(in @ W1 + b1), K=512   LAYER 2: out = h1 @ W2 + b2, K=1024
// D += Ah*Bh + Ah*Bl + Al*Bh  (fp32 accum; lo*lo ~2^-24, dropped)
template <int LAYER>
__global__ void __launch_bounds__(256)
k_mma(const float* __restrict__ bias_s, const float* __restrict__ bias_g) {
    const int KTOT = (LAYER == 1) ? DD : HH;
    bool grouped;
    int m0, mend, g = 0;
    if ((int)blockIdx.x < NSHT) {
        grouped = false; m0 = blockIdx.x * BM; mend = NTOK;
    } else {
        grouped = true;
        int tile = blockIdx.x - NSHT;
        if (tile >= g_ntiles) return;
        g = g_tile_group[tile]; m0 = g_tile_m0[tile]; mend = g_tile_end[tile];
    }
    const int colstart = blockIdx.y * BN;

    extern __shared__ char dsm[];
    const uint32_t base = (uint32_t)__cvta_generic_to_shared(dsm);

    const int tid = threadIdx.x;
    const int lane = tid & 31;
    const int warp = tid >> 5;
    const int wm = warp >> 2;     // 0..1 -> 64 rows
    const int wn = warp & 3;      // 0..3 -> 32 cols

    // ---- B bank pointers + bias ----
    int bias_off, seg;
    const __half *wH, *wL;
    const float* bias;
    if (LAYER == 1) {
        seg = colstart >> 10;
        int bank = grouped ? (SS + g * GG + seg) : seg;
        size_t bo = (size_t)bank * HH + (colstart & (HH - 1));
        wH = gw1_hi + bo * DD; wL = gw1_lo + bo * DD;
        bias_off = grouped ? g * (GG * HH) + colstart : colstart;
    } else {
        seg = colstart >> 9;
        int bank = grouped ? (SS + g * GG + seg) : seg;
        size_t bo = (size_t)bank * DD + (colstart & (DD - 1));
        wH = gw2_hi + bo * HH; wL = gw2_lo + bo * HH;
        bias_off = grouped ? g * (GG * DD) + colstart : colstart;
    }
    bias = grouped ? bias_g : bias_s;

    // ---- loader mapping: thread covers rows r0 and r1 ----
    const int r0 = tid >> 2, r1 = 64 + (tid >> 2);
    const uint32_t cb = (uint32_t)(tid & 3) * 16;
    const uint32_t o0 = (uint32_t)r0 * LDHB + cb, o1 = (uint32_t)r1 * LDHB + cb;
    const int kadd = (tid & 3) * 8;

    const __half *pa0h, *pa0l, *pa1h, *pa1l;
    bool v0 = true, v1 = true;
    {
        int p0 = m0 + r0, p1 = m0 + r1;
        if (LAYER == 1) {
            if (!grouped) {
                pa0h = gx_hi + (size_t)p0 * DD; pa0l = gx_lo + (size_t)p0 * DD;
                pa1h = gx_hi + (size_t)p1 * DD; pa1l = gx_lo + (size_t)p1 * DD;
            } else {
                v0 = p0 < mend; v1 = p1 < mend;
                int t0 = v0 ? g_perm[p0] : 0, t1 = v1 ? g_perm[p1] : 0;
                pa0h = gx_hi + (size_t)t0 * DD; pa0l = gx_lo + (size_t)t0 * DD;
                pa1h = gx_hi + (size_t)t1 * DD; pa1l = gx_lo + (size_t)t1 * DD;
            }
        } else {
            if (!grouped) {
                size_t q0 = (size_t)p0 * (SS * HH) + seg * HH;
                size_t q1 = (size_t)p1 * (SS * HH) + seg * HH;
                pa0h = gh1s_hi + q0; pa0l = gh1s_lo + q0;
                pa1h = gh1s_hi + q1; pa1l = gh1s_lo + q1;
            } else {
                v0 = p0 < mend; v1 = p1 < mend;
                size_t q0 = (size_t)(v0 ? p0 : 0) * (GG * HH) + seg * HH;
                size_t q1 = (size_t)(v1 ? p1 : 0) * (GG * HH) + seg * HH;
                pa0h = gh1g_hi + q0; pa0l = gh1g_lo + q0;
                pa1h = gh1g_hi + q1; pa1l = gh1g_lo + q1;
            }
        }
    }
    const __half* pb0h = wH + (size_t)r0 * KTOT;
    const __half* pb1h = wH + (size_t)r1 * KTOT;
    const __half* pb0l = wL + (size_t)r0 * KTOT;
    const __half* pb1l = wL + (size_t)r1 * KTOT;

    // stage layout: [Ah 10240][Al 10240][Bh 10240][Bl 10240]
    auto load = [&](int buf, int kk) {
        uint32_t sB = base + buf * STAGEB;
        int ke = kk * BK + kadd;
        cp16(sB + o0, pa0h + ke, v0);
        cp16(sB + o1, pa1h + ke, v1);
        cp16(sB + ARRB + o0, pa0l + ke, v0);
        cp16(sB + ARRB + o1, pa1l + ke, v1);
        cp16(sB + 2 * ARRB + o0, pb0h + ke, true);
        cp16(sB + 2 * ARRB + o1, pb1h + ke, true);
        cp16(sB + 3 * ARRB + o0, pb0l + ke, true);
        cp16(sB + 3 * ARRB + o1, pb1l + ke, true);
        CPC();
    };

    float d[4][4][4];
#pragma unroll
    for (int i = 0; i < 4; i++)
#pragma unroll
        for (int j = 0; j < 4; j++)
#pragma unroll
            for (int q = 0; q < 4; q++) d[i][j][q] = 0.f;

    const int NIT = KTOT / BK;
    load(0, 0); load(1, 1); load(2, 2);

    for (int it = 0; it < NIT; it++) {
        if (it < NIT - 2) CPW(2);
        else if (it == NIT - 2) CPW(1);
        else CPW(0);
        __syncthreads();
        if (it + 3 < NIT) load((it + 3) & 3, it + 3);
        const uint32_t sB = base + (it & 3) * STAGEB;

#pragma unroll
        for (int ks = 0; ks < 2; ks++) {
            const uint32_t colb = (uint32_t)((ks * 16 + ((lane >> 4) << 3)) << 1);
            uint32_t ah[4][4], al[4][4], bh[4][2], bl[4][2];
#pragma unroll
            for (int mt = 0; mt < 4; mt++) {
                uint32_t addr = sB + (uint32_t)(wm * 64 + mt * 16 + (lane & 15)) * LDHB + colb;
                LDSM4(ah[mt], addr);
                LDSM4(al[mt], addr + ARRB);
            }
#pragma unroll
            for (int np = 0; np < 2; np++) {
                uint32_t addr = sB + 2 * ARRB
                              + (uint32_t)(wn * 32 + np * 16 + (lane & 15)) * LDHB + colb;
                uint32_t q[4];
                LDSM4(q, addr);
                bh[np * 2][0] = q[0]; bh[np * 2][1] = q[2];
                bh[np * 2 + 1][0] = q[1]; bh[np * 2 + 1][1] = q[3];
                LDSM4(q, addr + ARRB);
                bl[np * 2][0] = q[0]; bl[np * 2][1] = q[2];
                bl[np * 2 + 1][0] = q[1]; bl[np * 2 + 1][1] = q[3];
            }
#pragma unroll
            for (int mt = 0; mt < 4; mt++)
#pragma unroll
                for (int nt = 0; nt < 4; nt++) MMA16(d[mt][nt], ah[mt], bh[nt]);
#pragma unroll
            for (int mt = 0; mt < 4; mt++)
#pragma unroll
                for (int nt = 0; nt < 4; nt++) MMA16(d[mt][nt], ah[mt], bl[nt]);
#pragma unroll
            for (int mt = 0; mt < 4; mt++)
#pragma unroll
                for (int nt = 0; nt < 4; nt++) MMA16(d[mt][nt], al[mt], bh[nt]);
        }
        __syncthreads();
    }

    // ---- epilogue ----
    float bb0[4], bb1[4];
#pragma unroll
    for (int nt = 0; nt < 4; nt++) {
        int cbx = wn * 32 + nt * 8 + 2 * (lane & 3);
        bb0[nt] = bias[bias_off + cbx];
        bb1[nt] = bias[bias_off + cbx + 1];
    }

#pragma unroll
    for (int mt = 0; mt < 4; mt++) {
#pragma unroll
        for (int half = 0; half < 2; half++) {
            int p = m0 + wm * 64 + mt * 16 + (lane >> 2) + half * 8;
            if (grouped && p >= mend) continue;
            if (LAYER == 1) {
                __half *dh, *dl;
                if (!grouped) {
                    size_t o = (size_t)p * (SS * HH) + colstart;
                    dh = gh1s_hi + o; dl = gh1s_lo + o;
                } else {
                    size_t o = (size_t)p * (GG * HH) + colstart;
                    dh = gh1g_hi + o; dl = gh1g_lo + o;
                }
#pragma unroll
                for (int nt = 0; nt < 4; nt++) {
                    int cbx = wn * 32 + nt * 8 + 2 * (lane & 3);
                    float u0 = d[mt][nt][half * 2 + 0] + bb0[nt];
                    float u1 = d[mt][nt][half * 2 + 1] + bb1[nt];
                    u0 = u0 > 0.f ? u0 : 0.f;
                    u1 = u1 > 0.f ? u1 : 0.f;
                    __half h0 = __float2half_rn(u0), h1 = __float2half_rn(u1);
                    __half2 H; H.x = h0; H.y = h1;
                    __half2 L;
                    L.x = __float2half_rn(u0 - __half2float(h0));
                    L.y = __float2half_rn(u1 - __half2float(h1));
                    *reinterpret_cast<__half2*>(dh + cbx) = H;
                    *reinterpret_cast<__half2*>(dl + cbx) = L;
                }
            } else {
                float* dst = (!grouped) ? g_outs + (size_t)p * (SS * DD) + colstart
                                        : g_outg + (size_t)g_perm[p] * (GG * DD) + colstart;
#pragma unroll
                for (int nt = 0; nt < 4; nt++) {
                    int cbx = wn * 32 + nt * 8 + 2 * (lane & 3);
                    float u0 = d[mt][nt][half * 2 + 0] + bb0[nt];
                    float u1 = d[mt][nt][half * 2 + 1] + bb1[nt];
                    *reinterpret_cast<float2*>(dst + cbx) = make_float2(u0, u1);
                }
            }
        }
    }
}

// ---------------- gate + combine ---------------------------------------------
__global__ void k_gate(const float* __restrict__ x, const float* __restrict__ cond_emb,
                       const float* __restrict__ gate_W, const float* __restrict__ gate_b,
                       float* __restrict__ out) {
    const int n = blockIdx.x;
    const int FD = DD + CC;
    __shared__ float gx[DD + CC], lg[KK * 4], w[KK * 4];
    const int t = threadIdx.x;
    const float* xr = x + (size_t)n * DD;
    for (int i = t; i < DD; i += 128) gx[i] = xr[i];
    if (t < CC) gx[DD + t] = cond_emb[g_gid[n] * CC + t];
    __syncthreads();
    const int warp = t >> 5, lane = t & 31, p0 = warp * 3;
    float s0 = 0.f, s1 = 0.f, s2 = 0.f;
    for (int f = lane; f < FD; f += 32) {
        float xv = gx[f];
        int p;
        p = p0 + 0; s0 = fmaf(xv, gate_W[((p >> 2) * FD + f) * 4 + (p & 3)], s0);
        p = p0 + 1; s1 = fmaf(xv, gate_W[((p >> 2) * FD + f) * 4 + (p & 3)], s1);
        p = p0 + 2; s2 = fmaf(xv, gate_W[((p >> 2) * FD + f) * 4 + (p & 3)], s2);
    }
#pragma unroll
    for (int o = 16; o > 0; o >>= 1) {
        s0 += __shfl_down_sync(0xffffffffu, s0, o);
        s1 += __shfl_down_sync(0xffffffffu, s1, o);
        s2 += __shfl_down_sync(0xffffffffu, s2, o);
    }
    if (lane == 0) {
        lg[p0 + 0] = s0 + gate_b[p0 + 0];
        lg[p0 + 1] = s1 + gate_b[p0 + 1];
        lg[p0 + 2] = s2 + gate_b[p0 + 2];
    }
    __syncthreads();
    if (t < KK) {
        float l0 = lg[t * 4], l1 = lg[t * 4 + 1], l2 = lg[t * 4 + 2], l3 = lg[t * 4 + 3];
        float m = fmaxf(fmaxf(l0, l1), fmaxf(l2, l3));
        float e0 = expf(l0 - m), e1 = expf(l1 - m), e2 = expf(l2 - m), e3 = expf(l3 - m);
        float inv = 1.f / (e0 + e1 + e2 + e3);
        w[t * 4] = e0 * inv; w[t * 4 + 1] = e1 * inv;
        w[t * 4 + 2] = e2 * inv; w[t * 4 + 3] = e3 * inv;
    }
    __syncthreads();
    const float* so = g_outs + (size_t)n * (SS * DD);
    const float* go = g_outg + (size_t)n * (GG * DD);
    for (int d = t; d < DD; d += 128) {
        float e0 = so[d], e1 = so[DD + d], e2 = go[d], e3 = go[DD + d];
#pragma unroll
        for (int k = 0; k < KK; k++)
            out[((size_t)k * NTOK + n) * DD + d] =
                w[k * 4] * e0 + w[k * 4 + 1] * e1 + w[k * 4 + 2] * e2 + w[k * 4 + 3] * e3;
    }
}

// ---------------- launch ------------------------------------------------------
extern "C" void kernel_launch(void* const* d_in, const int* in_sizes, int n_in,
                              void* d_out, int out_size) {
    const float* x   = (const float*)d_in[0];
    const int* nti   = (const int*)d_in[1];
    const int* e2g   = (const int*)d_in[2];
    const float* Ws1 = (const float*)d_in[3];
    const float* bs1 = (const float*)d_in[4];
    const float* Ws2 = (const float*)d_in[5];
    const float* bs2 = (const float*)d_in[6];
    const float* Wg1 = (const float*)d_in[7];
    const float* bg1 = (const float*)d_in[8];
    const float* Wg2 = (const float*)d_in[9];
    const float* bg2 = (const float*)d_in[10];
    const float* cemb = (const float*)d_in[11];
    const float* gW  = (const float*)d_in[12];
    const float* gb  = (const float*)d_in[13];
    float* out = (float*)d_out;

    cudaFuncSetAttribute(k_mma<1>, cudaFuncAttributeMaxDynamicSharedMemorySize, SMEM_TOT);
    cudaFuncSetAttribute(k_mma<2>, cudaFuncAttributeMaxDynamicSharedMemorySize, SMEM_TOT);

    k_prep<<<1, 256>>>(nti, e2g);
    k_cvt_x<<<NTOK * DD / 4 / 256, 256>>>((const float4*)x);
    k_cvt_w<<<dim3(DD / 64, HH / 32, SS), dim3(32, 8)>>>(Ws1, DD, HH, 0, 0);
    k_cvt_w<<<dim3(DD / 64, HH / 32, NGR * GG), dim3(32, 8)>>>(Wg1, DD, HH, 0, SS);
    k_cvt_w<<<dim3(HH / 64, DD / 32, SS), dim3(32, 8)>>>(Ws2, HH, DD, 1, 0);
    k_cvt_w<<<dim3(HH / 64, DD / 32, NGR * GG), dim3(32, 8)>>>(Wg2, HH, DD, 1, SS);
    k_mma<1><<<dim3(NSHT + MAXTILES, (SS * HH) / BN), 256, SMEM_TOT>>>(bs1, bg1);
    k_mma<2><<<dim3(NSHT + MAXTILES, (SS * DD) / BN), 256, SMEM_TOT>>>(bs2, bg2);
    k_gate<<<NTOK, 128>>>(x, cemb, gW, gb, out);
}

// round 12
// speedup vs baseline: 1.1566x; 1.1566x over previous
#include <cuda_runtime.h>
#include <cuda_fp16.h>
#include <stdint.h>

#define DD 512
#define HH 1024
#define NTOK 4096
#define SS 2
#define GG 2
#define NGR 6
#define CC 32
#define KK 3
#define NEVT 50
#define BM 128
#define BN 128
#define BK 32
#define MAXTILES 40
#define NBANK (SS + NGR * GG)
#define NSHT (NTOK / BM)       // 32 shared tiles
#define LDHB 80                // bytes per smem row (32 halfs + 8 pad)
#define ARRB 10240             // bytes per array per stage (128*80)
#define STAGEB (4 * ARRB)      // 40960
#define NSTAGE 2
#define SMEM_TOT (NSTAGE * STAGEB)   // 81920 -> 2 CTAs/SM

// ---------------- device scratch (no cudaMalloc; 16B-aligned) ----------------
__device__ __align__(16) __half gx_hi[NTOK * DD], gx_lo[NTOK * DD];
__device__ __align__(16) __half gw1_hi[NBANK * HH * DD], gw1_lo[NBANK * HH * DD]; // [bank][N][K]
__device__ __align__(16) __half gw2_hi[NBANK * DD * HH], gw2_lo[NBANK * DD * HH];
__device__ __align__(16) __half gh1s_hi[NTOK * SS * HH], gh1s_lo[NTOK * SS * HH];
__device__ __align__(16) __half gh1g_hi[NTOK * GG * HH], gh1g_lo[NTOK * GG * HH];
__device__ __align__(16) float g_outs[NTOK * SS * DD], g_outg[NTOK * GG * DD];
__device__ int g_gid[NTOK], g_perm[NTOK];
__device__ int g_tile_group[MAXTILES], g_tile_m0[MAXTILES], g_tile_end[MAXTILES], g_ntiles;

// ---------------- PTX helpers ------------------------------------------------
__device__ __forceinline__ void cp16(uint32_t d, const void* s, bool v) {
    int sz = v ? 16 : 0;
    asm volatile("cp.async.cg.shared.global [%0], [%1], 16, %2;" :: "r"(d), "l"(s), "r"(sz));
}
#define CPC() asm volatile("cp.async.commit_group;")
#define CPW(N) asm volatile("cp.async.wait_group %0;" :: "n"(N))
#define LDSM4(r, a) asm volatile("ldmatrix.sync.aligned.m8n8.x4.shared.b16 {%0,%1,%2,%3}, [%4];" \
    : "=r"((r)[0]), "=r"((r)[1]), "=r"((r)[2]), "=r"((r)[3]) : "r"(a))
#define MMA16(d, a, b) asm volatile( \
    "mma.sync.aligned.m16n8k16.row.col.f32.f16.f16.f32 " \
    "{%0,%1,%2,%3}, {%4,%5,%6,%7}, {%8,%9}, {%0,%1,%2,%3};" \
    : "+f"((d)[0]), "+f"((d)[1]), "+f"((d)[2]), "+f"((d)[3]) \
    : "r"((a)[0]), "r"((a)[1]), "r"((a)[2]), "r"((a)[3]), "r"((b)[0]), "r"((b)[1]))

// ---------------- prep: group ids + counting sort + tile table ---------------
__global__ void k_prep(const int* __restrict__ nti, const int* __restrict__ e2g) {
    __shared__ int cnt[NGR], st[NGR], cur[NGR];
    int t = threadIdx.x;
    if (t < NGR) cnt[t] = 0;
    __syncthreads();
    for (int n = t; n < NTOK; n += blockDim.x) {
        int v = nti[n]; v = v < 0 ? 0 : (v > NEVT - 1 ? NEVT - 1 : v);
        int g = e2g[v]; g_gid[n] = g; atomicAdd(&cnt[g], 1);
    }
    __syncthreads();
    if (t == 0) {
        int acc = 0, ntl = 0;
        for (int g = 0; g < NGR; g++) {
            st[g] = acc; int c = cnt[g];
            for (int m0 = acc; m0 < acc + c; m0 += BM) {
                g_tile_group[ntl] = g; g_tile_m0[ntl] = m0; g_tile_end[ntl] = acc + c; ntl++;
            }
            acc += c;
        }
        g_ntiles = ntl;
        for (int g = 0; g < NGR; g++) cur[g] = st[g];
    }
    __syncthreads();
    for (int n = t; n < NTOK; n += blockDim.x) {
        int pos = atomicAdd(&cur[g_gid[n]], 1);
        g_perm[pos] = n;
    }
}

// ---------------- split x -> fp16 hi/lo (vectorized) -------------------------
__global__ void k_cvt_x(const float4* __restrict__ x) {
    int i = blockIdx.x * 256 + threadIdx.x;
    float4 v = x[i];
    __half h0 = __float2half_rn(v.x), h1 = __float2half_rn(v.y);
    __half h2 = __float2half_rn(v.z), h3 = __float2half_rn(v.w);
    __half2 H0; H0.x = h0; H0.y = h1;
    __half2 H1; H1.x = h2; H1.y = h3;
    __half2 L0, L1;
    L0.x = __float2half_rn(v.x - __half2float(h0));
    L0.y = __float2half_rn(v.y - __half2float(h1));
    L1.x = __float2half_rn(v.z - __half2float(h2));
    L1.y = __float2half_rn(v.w - __half2float(h3));
    reinterpret_cast<__half2*>(gx_hi)[2 * i] = H0;
    reinterpret_cast<__half2*>(gx_hi)[2 * i + 1] = H1;
    reinterpret_cast<__half2*>(gx_lo)[2 * i] = L0;
    reinterpret_cast<__half2*>(gx_lo)[2 * i + 1] = L1;
}

// merged weight convert+transpose: z<SS -> shared bank, else grouped bank.
// src [Kd][Nd] fp32 -> dst [bank][Nd][Kd] fp16 hi/lo
template <int LAYER>
__global__ void k_cvt_w(const float* __restrict__ srcS, const float* __restrict__ srcG) {
    const int Kd = (LAYER == 1) ? DD : HH;
    const int Nd = (LAYER == 1) ? HH : DD;
    __shared__ float s[64][33];
    int z = blockIdx.z, k0 = blockIdx.x * 64, n0 = blockIdx.y * 32;
    const float* sp = (z < SS) ? srcS + (size_t)z * Kd * Nd
                               : srcG + (size_t)(z - SS) * Kd * Nd;
    int tx = threadIdx.x, ty = threadIdx.y;   // (32, 8)
    for (int r = ty; r < 64; r += 8)
        s[r][tx] = sp[(size_t)(k0 + r) * Nd + n0 + tx];
    __syncthreads();
    __half2* dh = reinterpret_cast<__half2*>((LAYER == 1) ? gw1_hi : gw2_hi);
    __half2* dl = reinterpret_cast<__half2*>((LAYER == 1) ? gw1_lo : gw2_lo);
    for (int nl = ty; nl < 32; nl += 8) {
        float v0 = s[2 * tx][nl], v1 = s[2 * tx + 1][nl];
        __half h0 = __float2half_rn(v0), h1 = __float2half_rn(v1);
        __half2 H; H.x = h0; H.y = h1;
        __half2 L;
        L.x = __float2half_rn(v0 - __half2float(h0));
        L.y = __float2half_rn(v1 - __half2float(h1));
        size_t o = (((size_t)z * Nd + n0 + nl) * Kd + k0) / 2 + tx;
        dh[o] = H;
        dl[o] = L;
    }
}

// ---------------- fp16x3 tensor GEMM, merged shared+grouped per layer --------
// LAYER 1: h1 = relu(in @ W1 + b1), K=512   LAYER 2: out = h1 @ W2 + b2, K=1024
// D += Ah*Bh + Ah*Bl + Al*Bh  (fp32 accum; lo*lo ~2^-24, dropped)
template <int LAYER>
__global__ void __launch_bounds__(256)
k_mma(const float* __restrict__ bias_s, const float* __restrict__ bias_g) {
    const int KTOT = (LAYER == 1) ? DD : HH;
    bool grouped;
    int m0, mend, g = 0;
    if ((int)blockIdx.x < NSHT) {
        grouped = false; m0 = blockIdx.x * BM; mend = NTOK;
    } else {
        grouped = true;
        int tile = blockIdx.x - NSHT;
        if (tile >= g_ntiles) return;
        g = g_tile_group[tile]; m0 = g_tile_m0[tile]; mend = g_tile_end[tile];
    }
    const int colstart = blockIdx.y * BN;

    extern __shared__ char dsm[];
    const uint32_t base = (uint32_t)__cvta_generic_to_shared(dsm);

    const int tid = threadIdx.x;
    const int lane = tid & 31;
    const int warp = tid >> 5;
    const int wm = warp >> 2;     // 0..1 -> 64 rows
    const int wn = warp & 3;      // 0..3 -> 32 cols

    // ---- B bank pointers + bias ----
    int bias_off, seg;
    const __half *wH, *wL;
    const float* bias;
    if (LAYER == 1) {
        seg = colstart >> 10;
        int bank = grouped ? (SS + g * GG + seg) : seg;
        size_t bo = (size_t)bank * HH + (colstart & (HH - 1));
        wH = gw1_hi + bo * DD; wL = gw1_lo + bo * DD;
        bias_off = grouped ? g * (GG * HH) + colstart : colstart;
    } else {
        seg = colstart >> 9;
        int bank = grouped ? (SS + g * GG + seg) : seg;
        size_t bo = (size_t)bank * DD + (colstart & (DD - 1));
        wH = gw2_hi + bo * HH; wL = gw2_lo + bo * HH;
        bias_off = grouped ? g * (GG * DD) + colstart : colstart;
    }
    bias = grouped ? bias_g : bias_s;

    // ---- loader mapping: thread covers rows r0 and r1 ----
    const int r0 = tid >> 2, r1 = 64 + (tid >> 2);
    const uint32_t cb = (uint32_t)(tid & 3) * 16;
    const uint32_t o0 = (uint32_t)r0 * LDHB + cb, o1 = (uint32_t)r1 * LDHB + cb;
    const int kadd = (tid & 3) * 8;

    const __half *pa0h, *pa0l, *pa1h, *pa1l;
    bool v0 = true, v1 = true;
    {
        int p0 = m0 + r0, p1 = m0 + r1;
        if (LAYER == 1) {
            if (!grouped) {
                pa0h = gx_hi + (size_t)p0 * DD; pa0l = gx_lo + (size_t)p0 * DD;
                pa1h = gx_hi + (size_t)p1 * DD; pa1l = gx_lo + (size_t)p1 * DD;
            } else {
                v0 = p0 < mend; v1 = p1 < mend;
                int t0 = v0 ? g_perm[p0] : 0, t1 = v1 ? g_perm[p1] : 0;
                pa0h = gx_hi + (size_t)t0 * DD; pa0l = gx_lo + (size_t)t0 * DD;
                pa1h = gx_hi + (size_t)t1 * DD; pa1l = gx_lo + (size_t)t1 * DD;
            }
        } else {
            if (!grouped) {
                size_t q0 = (size_t)p0 * (SS * HH) + seg * HH;
                size_t q1 = (size_t)p1 * (SS * HH) + seg * HH;
                pa0h = gh1s_hi + q0; pa0l = gh1s_lo + q0;
                pa1h = gh1s_hi + q1; pa1l = gh1s_lo + q1;
            } else {
                v0 = p0 < mend; v1 = p1 < mend;
                size_t q0 = (size_t)(v0 ? p0 : 0) * (GG * HH) + seg * HH;
                size_t q1 = (size_t)(v1 ? p1 : 0) * (GG * HH) + seg * HH;
                pa0h = gh1g_hi + q0; pa0l = gh1g_lo + q0;
                pa1h = gh1g_hi + q1; pa1l = gh1g_lo + q1;
            }
        }
    }
    const __half* pb0h = wH + (size_t)r0 * KTOT;
    const __half* pb1h = wH + (size_t)r1 * KTOT;
    const __half* pb0l = wL + (size_t)r0 * KTOT;
    const __half* pb1l = wL + (size_t)r1 * KTOT;

    // stage layout: [Ah 10240][Al 10240][Bh 10240][Bl 10240]
    auto load = [&](int buf, int it) {
        uint32_t sB = base + buf * STAGEB;
        int ke = it * BK + kadd;
        cp16(sB + o0, pa0h + ke, v0);
        cp16(sB + o1, pa1h + ke, v1);
        cp16(sB + ARRB + o0, pa0l + ke, v0);
        cp16(sB + ARRB + o1, pa1l + ke, v1);
        cp16(sB + 2 * ARRB + o0, pb0h + ke, true);
        cp16(sB + 2 * ARRB + o1, pb1h + ke, true);
        cp16(sB + 3 * ARRB + o0, pb0l + ke, true);
        cp16(sB + 3 * ARRB + o1, pb1l + ke, true);
        CPC();
    };

    float d[4][4][4];
#pragma unroll
    for (int i = 0; i < 4; i++)
#pragma unroll
        for (int j = 0; j < 4; j++)
#pragma unroll
            for (int q = 0; q < 4; q++) d[i][j][q] = 0.f;

    const int NIT = KTOT / BK;
    load(0, 0);

    for (int it = 0; it < NIT; it++) {
        const int buf = it & 1;
        if (it + 1 < NIT) { load(buf ^ 1, it + 1); CPW(1); }
        else CPW(0);
        __syncthreads();
        const uint32_t sB = base + buf * STAGEB;

#pragma unroll
        for (int ks = 0; ks < 2; ks++) {
            const uint32_t colb = (uint32_t)((ks * 16 + ((lane >> 4) << 3)) << 1);
            uint32_t ah[4][4], al[4][4], bh[4][2], bl[4][2];
#pragma unroll
            for (int mt = 0; mt < 4; mt++) {
                uint32_t addr = sB + (uint32_t)(wm * 64 + mt * 16 + (lane & 15)) * LDHB + colb;
                LDSM4(ah[mt], addr);
                LDSM4(al[mt], addr + ARRB);
            }
#pragma unroll
            for (int np = 0; np < 2; np++) {
                uint32_t addr = sB + 2 * ARRB
                              + (uint32_t)(wn * 32 + np * 16 + (lane & 15)) * LDHB + colb;
                uint32_t q[4];
                LDSM4(q, addr);
                bh[np * 2][0] = q[0]; bh[np * 2][1] = q[2];
                bh[np * 2 + 1][0] = q[1]; bh[np * 2 + 1][1] = q[3];
                LDSM4(q, addr + ARRB);
                bl[np * 2][0] = q[0]; bl[np * 2][1] = q[2];
                bl[np * 2 + 1][0] = q[1]; bl[np * 2 + 1][1] = q[3];
            }
#pragma unroll
            for (int mt = 0; mt < 4; mt++)
#pragma unroll
                for (int nt = 0; nt < 4; nt++) MMA16(d[mt][nt], ah[mt], bh[nt]);
#pragma unroll
            for (int mt = 0; mt < 4; mt++)
#pragma unroll
                for (int nt = 0; nt < 4; nt++) MMA16(d[mt][nt], ah[mt], bl[nt]);
#pragma unroll
            for (int mt = 0; mt < 4; mt++)
#pragma unroll
                for (int nt = 0; nt < 4; nt++) MMA16(d[mt][nt], al[mt], bh[nt]);
        }
        __syncthreads();
    }

    // ---- epilogue ----
    float bb0[4], bb1[4];
#pragma unroll
    for (int nt = 0; nt < 4; nt++) {
        int cbx = wn * 32 + nt * 8 + 2 * (lane & 3);
        bb0[nt] = bias[bias_off + cbx];
        bb1[nt] = bias[bias_off + cbx + 1];
    }

#pragma unroll
    for (int mt = 0; mt < 4; mt++) {
#pragma unroll
        for (int half = 0; half < 2; half++) {
            int p = m0 + wm * 64 + mt * 16 + (lane >> 2) + half * 8;
            if (grouped && p >= mend) continue;
            if (LAYER == 1) {
                __half *dh, *dl;
                if (!grouped) {
                    size_t o = (size_t)p * (SS * HH) + colstart;
                    dh = gh1s_hi + o; dl = gh1s_lo + o;
                } else {
                    size_t o = (size_t)p * (GG * HH) + colstart;
                    dh = gh1g_hi + o; dl = gh1g_lo + o;
                }
#pragma unroll
                for (int nt = 0; nt < 4; nt++) {
                    int cbx = wn * 32 + nt * 8 + 2 * (lane & 3);
                    float u0 = d[mt][nt][half * 2 + 0] + bb0[nt];
                    float u1 = d[mt][nt][half * 2 + 1] + bb1[nt];
                    u0 = u0 > 0.f ? u0 : 0.f;
                    u1 = u1 > 0.f ? u1 : 0.f;
                    __half h0 = __float2half_rn(u0), h1 = __float2half_rn(u1);
                    __half2 H; H.x = h0; H.y = h1;
                    __half2 L;
                    L.x = __float2half_rn(u0 - __half2float(h0));
                    L.y = __float2half_rn(u1 - __half2float(h1));
                    *reinterpret_cast<__half2*>(dh + cbx) = H;
                    *reinterpret_cast<__half2*>(dl + cbx) = L;
                }
            } else {
                float* dst = (!grouped) ? g_outs + (size_t)p * (SS * DD) + colstart
                                        : g_outg + (size_t)g_perm[p] * (GG * DD) + colstart;
#pragma unroll
                for (int nt = 0; nt < 4; nt++) {
                    int cbx = wn * 32 + nt * 8 + 2 * (lane & 3);
                    float u0 = d[mt][nt][half * 2 + 0] + bb0[nt];
                    float u1 = d[mt][nt][half * 2 + 1] + bb1[nt];
                    *reinterpret_cast<float2*>(dst + cbx) = make_float2(u0, u1);
                }
            }
        }
    }
}

// ---------------- gate + combine ---------------------------------------------
__global__ void k_gate(const float* __restrict__ x, const float* __restrict__ cond_emb,
                       const float* __restrict__ gate_W, const float* __restrict__ gate_b,
                       float* __restrict__ out) {
    const int n = blockIdx.x;
    const int FD = DD + CC;
    __shared__ float gx[DD + CC], lg[KK * 4], w[KK * 4];
    const int t = threadIdx.x;
    const float* xr = x + (size_t)n * DD;
    for (int i = t; i < DD; i += 128) gx[i] = xr[i];
    if (t < CC) gx[DD + t] = cond_emb[g_gid[n] * CC + t];
    __syncthreads();
    const int warp = t >> 5, lane = t & 31, p0 = warp * 3;
    float s0 = 0.f, s1 = 0.f, s2 = 0.f;
    for (int f = lane; f < FD; f += 32) {
        float xv = gx[f];
        int p;
        p = p0 + 0; s0 = fmaf(xv, gate_W[((p >> 2) * FD + f) * 4 + (p & 3)], s0);
        p = p0 + 1; s1 = fmaf(xv, gate_W[((p >> 2) * FD + f) * 4 + (p & 3)], s1);
        p = p0 + 2; s2 = fmaf(xv, gate_W[((p >> 2) * FD + f) * 4 + (p & 3)], s2);
    }
#pragma unroll
    for (int o = 16; o > 0; o >>= 1) {
        s0 += __shfl_down_sync(0xffffffffu, s0, o);
        s1 += __shfl_down_sync(0xffffffffu, s1, o);
        s2 += __shfl_down_sync(0xffffffffu, s2, o);
    }
    if (lane == 0) {
        lg[p0 + 0] = s0 + gate_b[p0 + 0];
        lg[p0 + 1] = s1 + gate_b[p0 + 1];
        lg[p0 + 2] = s2 + gate_b[p0 + 2];
    }
    __syncthreads();
    if (t < KK) {
        float l0 = lg[t * 4], l1 = lg[t * 4 + 1], l2 = lg[t * 4 + 2], l3 = lg[t * 4 + 3];
        float m = fmaxf(fmaxf(l0, l1), fmaxf(l2, l3));
        float e0 = expf(l0 - m), e1 = expf(l1 - m), e2 = expf(l2 - m), e3 = expf(l3 - m);
        float inv = 1.f / (e0 + e1 + e2 + e3);
        w[t * 4] = e0 * inv; w[t * 4 + 1] = e1 * inv;
        w[t * 4 + 2] = e2 * inv; w[t * 4 + 3] = e3 * inv;
    }
    __syncthreads();
    const float* so = g_outs + (size_t)n * (SS * DD);
    const float* go = g_outg + (size_t)n * (GG * DD);
    for (int d = t; d < DD; d += 128) {
        float e0 = so[d], e1 = so[DD + d], e2 = go[d], e3 = go[DD + d];
#pragma unroll
        for (int k = 0; k < KK; k++)
            out[((size_t)k * NTOK + n) * DD + d] =
                w[k * 4] * e0 + w[k * 4 + 1] * e1 + w[k * 4 + 2] * e2 + w[k * 4 + 3] * e3;
    }
}

// ---------------- launch ------------------------------------------------------
extern "C" void kernel_launch(void* const* d_in, const int* in_sizes, int n_in,
                              void* d_out, int out_size) {
    const float* x   = (const float*)d_in[0];
    const int* nti   = (const int*)d_in[1];
    const int* e2g   = (const int*)d_in[2];
    const float* Ws1 = (const float*)d_in[3];
    const float* bs1 = (const float*)d_in[4];
    const float* Ws2 = (const float*)d_in[5];
    const float* bs2 = (const float*)d_in[6];
    const float* Wg1 = (const float*)d_in[7];
    const float* bg1 = (const float*)d_in[8];
    const float* Wg2 = (const float*)d_in[9];
    const float* bg2 = (const float*)d_in[10];
    const float* cemb = (const float*)d_in[11];
    const float* gW  = (const float*)d_in[12];
    const float* gb  = (const float*)d_in[13];
    float* out = (float*)d_out;

    cudaFuncSetAttribute(k_mma<1>, cudaFuncAttributeMaxDynamicSharedMemorySize, SMEM_TOT);
    cudaFuncSetAttribute(k_mma<2>, cudaFuncAttributeMaxDynamicSharedMemorySize, SMEM_TOT);

    k_prep<<<1, 256>>>(nti, e2g);
    k_cvt_x<<<NTOK * DD / 4 / 256, 256>>>((const float4*)x);
    k_cvt_w<1><<<dim3(DD / 64, HH / 32, NBANK), dim3(32, 8)>>>(Ws1, Wg1);
    k_cvt_w<2><<<dim3(HH / 64, DD / 32, NBANK), dim3(32, 8)>>>(Ws2, Wg2);
    k_mma<1><<<dim3(NSHT + MAXTILES, (SS * HH) / BN), 256, SMEM_TOT>>>(bs1, bg1);
    k_mma<2><<<dim3(NSHT + MAXTILES, (SS * DD) / BN), 256, SMEM_TOT>>>(bs2, bg2);
    k_gate<<<NTOK, 128>>>(x, cemb, gW, gb, out);
}

// round 13
// speedup vs baseline: 1.2090x; 1.0453x over previous
#include <cuda_runtime.h>
#include <cuda_fp16.h>
#include <stdint.h>

#define DD 512
#define HH 1024
#define NTOK 4096
#define SS 2
#define GG 2
#define NGR 6
#define CC 32
#define KK 3
#define NEVT 50
#define BM 128
#define BN 128
#define BK 32
#define MAXTILES 40
#define NBANK (SS + NGR * GG)
#define NSHT (NTOK / BM)       // 32 shared tiles
#define LDHB 80                // bytes per smem row (32 halfs + 8 pad)
#define ARRB 10240             // bytes per array per stage (128*80)
#define STAGEB (4 * ARRB)      // 40960
#define NSTAGE 2
#define SMEM_TOT (NSTAGE * STAGEB)   // 81920 -> 2 CTAs/SM

// ---------------- device scratch (no cudaMalloc; 16B-aligned) ----------------
__device__ __align__(16) __half gx_hi[NTOK * DD], gx_lo[NTOK * DD];
__device__ __align__(16) __half gw1_hi[NBANK * HH * DD], gw1_lo[NBANK * HH * DD]; // [bank][N][K]
__device__ __align__(16) __half gw2_hi[NBANK * DD * HH], gw2_lo[NBANK * DD * HH];
__device__ __align__(16) __half gh1s_hi[NTOK * SS * HH], gh1s_lo[NTOK * SS * HH];
__device__ __align__(16) __half gh1g_hi[NTOK * GG * HH], gh1g_lo[NTOK * GG * HH];
__device__ __align__(16) float g_outs[NTOK * SS * DD], g_outg[NTOK * GG * DD];
__device__ int g_gid[NTOK], g_perm[NTOK];
__device__ int g_tile_group[MAXTILES], g_tile_m0[MAXTILES], g_tile_end[MAXTILES], g_ntiles;

// ---------------- PTX helpers ------------------------------------------------
__device__ __forceinline__ void cp16(uint32_t d, const void* s, bool v) {
    int sz = v ? 16 : 0;
    asm volatile("cp.async.cg.shared.global [%0], [%1], 16, %2;" :: "r"(d), "l"(s), "r"(sz));
}
#define CPC() asm volatile("cp.async.commit_group;")
#define CPW(N) asm volatile("cp.async.wait_group %0;" :: "n"(N))
#define LDSM4(r, a) asm volatile("ldmatrix.sync.aligned.m8n8.x4.shared.b16 {%0,%1,%2,%3}, [%4];" \
    : "=r"((r)[0]), "=r"((r)[1]), "=r"((r)[2]), "=r"((r)[3]) : "r"(a))
#define MMA16(d, a, b) asm volatile( \
    "mma.sync.aligned.m16n8k16.row.col.f32.f16.f16.f32 " \
    "{%0,%1,%2,%3}, {%4,%5,%6,%7}, {%8,%9}, {%0,%1,%2,%3};" \
    : "+f"((d)[0]), "+f"((d)[1]), "+f"((d)[2]), "+f"((d)[3]) \
    : "r"((a)[0]), "r"((a)[1]), "r"((a)[2]), "r"((a)[3]), "r"((b)[0]), "r"((b)[1]))

// ---------------- prep: group ids + counting sort + tile table ---------------
__global__ void k_prep(const int* __restrict__ nti, const int* __restrict__ e2g) {
    __shared__ int cnt[NGR], st[NGR], cur[NGR];
    int t = threadIdx.x;
    if (t < NGR) cnt[t] = 0;
    __syncthreads();
    for (int n = t; n < NTOK; n += blockDim.x) {
        int v = nti[n]; v = v < 0 ? 0 : (v > NEVT - 1 ? NEVT - 1 : v);
        int g = e2g[v]; g_gid[n] = g; atomicAdd(&cnt[g], 1);
    }
    __syncthreads();
    if (t == 0) {
        int acc = 0, ntl = 0;
        for (int g = 0; g < NGR; g++) {
            st[g] = acc; int c = cnt[g];
            for (int m0 = acc; m0 < acc + c; m0 += BM) {
                g_tile_group[ntl] = g; g_tile_m0[ntl] = m0; g_tile_end[ntl] = acc + c; ntl++;
            }
            acc += c;
        }
        g_ntiles = ntl;
        for (int g = 0; g < NGR; g++) cur[g] = st[g];
    }
    __syncthreads();
    for (int n = t; n < NTOK; n += blockDim.x) {
        int pos = atomicAdd(&cur[g_gid[n]], 1);
        g_perm[pos] = n;
    }
}

// ---------------- split x -> fp16 hi/lo (vectorized) -------------------------
__global__ void k_cvt_x(const float4* __restrict__ x) {
    int i = blockIdx.x * 256 + threadIdx.x;
    float4 v = x[i];
    __half h0 = __float2half_rn(v.x), h1 = __float2half_rn(v.y);
    __half h2 = __float2half_rn(v.z), h3 = __float2half_rn(v.w);
    __half2 H0; H0.x = h0; H0.y = h1;
    __half2 H1; H1.x = h2; H1.y = h3;
    __half2 L0, L1;
    L0.x = __float2half_rn(v.x - __half2float(h0));
    L0.y = __float2half_rn(v.y - __half2float(h1));
    L1.x = __float2half_rn(v.z - __half2float(h2));
    L1.y = __float2half_rn(v.w - __half2float(h3));
    reinterpret_cast<__half2*>(gx_hi)[2 * i] = H0;
    reinterpret_cast<__half2*>(gx_hi)[2 * i + 1] = H1;
    reinterpret_cast<__half2*>(gx_lo)[2 * i] = L0;
    reinterpret_cast<__half2*>(gx_lo)[2 * i + 1] = L1;
}

// merged weight convert+transpose: z<SS -> shared bank, else grouped bank.
// 64x64 tiles, float4 loads. src [Kd][Nd] fp32 -> dst [bank][Nd][Kd] fp16 hi/lo
template <int LAYER>
__global__ void __launch_bounds__(256)
k_cvt_w(const float* __restrict__ srcS, const float* __restrict__ srcG) {
    const int Kd = (LAYER == 1) ? DD : HH;
    const int Nd = (LAYER == 1) ? HH : DD;
    __shared__ float s[64][65];
    int z = blockIdx.z, k0 = blockIdx.x * 64, n0 = blockIdx.y * 64;
    const float* sp = (z < SS) ? srcS + (size_t)z * Kd * Nd
                               : srcG + (size_t)(z - SS) * Kd * Nd;
    int t = threadIdx.x;              // 256
    int r = t >> 4, c4 = (t & 15) * 4;
#pragma unroll
    for (int i = 0; i < 4; i++) {
        float4 v = *reinterpret_cast<const float4*>(
            sp + (size_t)(k0 + r + 16 * i) * Nd + n0 + c4);
        s[r + 16 * i][c4 + 0] = v.x;
        s[r + 16 * i][c4 + 1] = v.y;
        s[r + 16 * i][c4 + 2] = v.z;
        s[r + 16 * i][c4 + 3] = v.w;
    }
    __syncthreads();
    __half2* dh = reinterpret_cast<__half2*>((LAYER == 1) ? gw1_hi : gw2_hi);
    __half2* dl = reinterpret_cast<__half2*>((LAYER == 1) ? gw1_lo : gw2_lo);
    int tx = t & 31, ny = t >> 5;     // tx: k-pair 0..31, ny: n base 0..7
#pragma unroll
    for (int i = 0; i < 8; i++) {
        int nl = ny * 8 + i;
        float v0 = s[2 * tx][nl], v1 = s[2 * tx + 1][nl];
        __half h0 = __float2half_rn(v0), h1 = __float2half_rn(v1);
        __half2 H; H.x = h0; H.y = h1;
        __half2 L;
        L.x = __float2half_rn(v0 - __half2float(h0));
        L.y = __float2half_rn(v1 - __half2float(h1));
        size_t o = (((size_t)z * Nd + n0 + nl) * Kd + k0) / 2 + tx;
        dh[o] = H;
        dl[o] = L;
    }
}

// ---------------- fp16x3 tensor GEMM, merged shared+grouped per layer --------
// LAYER 1: h1 = relu(in @ W1 + b1), K=512   LAYER 2: out = h1 @ W2 + b2, K=1024
// D += Ah*Bh + Ah*Bl + Al*Bh  (fp32 accum; lo*lo ~2^-24, dropped)
template <int LAYER>
__global__ void __launch_bounds__(256)
k_mma(const float* __restrict__ bias_s, const float* __restrict__ bias_g) {
    const int KTOT = (LAYER == 1) ? DD : HH;
    bool grouped;
    int m0, mend, g = 0;
    if ((int)blockIdx.x < NSHT) {
        grouped = false; m0 = blockIdx.x * BM; mend = NTOK;
    } else {
        grouped = true;
        int tile = blockIdx.x - NSHT;
        if (tile >= g_ntiles) return;
        g = g_tile_group[tile]; m0 = g_tile_m0[tile]; mend = g_tile_end[tile];
    }
    const int colstart = blockIdx.y * BN;

    extern __shared__ char dsm[];
    const uint32_t base = (uint32_t)__cvta_generic_to_shared(dsm);

    const int tid = threadIdx.x;
    const int lane = tid & 31;
    const int warp = tid >> 5;
    const int wm = warp >> 2;     // 0..1 -> 64 rows
    const int wn = warp & 3;      // 0..3 -> 32 cols

    // ---- B bank pointers + bias ----
    int bias_off, seg;
    const __half *wH, *wL;
    const float* bias;
    if (LAYER == 1) {
        seg = colstart >> 10;
        int bank = grouped ? (SS + g * GG + seg) : seg;
        size_t bo = (size_t)bank * HH + (colstart & (HH - 1));
        wH = gw1_hi + bo * DD; wL = gw1_lo + bo * DD;
        bias_off = grouped ? g * (GG * HH) + colstart : colstart;
    } else {
        seg = colstart >> 9;
        int bank = grouped ? (SS + g * GG + seg) : seg;
        size_t bo = (size_t)bank * DD + (colstart & (DD - 1));
        wH = gw2_hi + bo * HH; wL = gw2_lo + bo * HH;
        bias_off = grouped ? g * (GG * DD) + colstart : colstart;
    }
    bias = grouped ? bias_g : bias_s;

    // ---- loader mapping: thread covers rows r0 and r1 ----
    const int r0 = tid >> 2, r1 = 64 + (tid >> 2);
    const uint32_t cb = (uint32_t)(tid & 3) * 16;
    const uint32_t o0 = (uint32_t)r0 * LDHB + cb, o1 = (uint32_t)r1 * LDHB + cb;
    const int kadd = (tid & 3) * 8;

    const __half *pa0h, *pa0l, *pa1h, *pa1l;
    bool v0 = true, v1 = true;
    {
        int p0 = m0 + r0, p1 = m0 + r1;
        if (LAYER == 1) {
            if (!grouped) {
                pa0h = gx_hi + (size_t)p0 * DD; pa0l = gx_lo + (size_t)p0 * DD;
                pa1h = gx_hi + (size_t)p1 * DD; pa1l = gx_lo + (size_t)p1 * DD;
            } else {
                v0 = p0 < mend; v1 = p1 < mend;
                int t0 = v0 ? g_perm[p0] : 0, t1 = v1 ? g_perm[p1] : 0;
                pa0h = gx_hi + (size_t)t0 * DD; pa0l = gx_lo + (size_t)t0 * DD;
                pa1h = gx_hi + (size_t)t1 * DD; pa1l = gx_lo + (size_t)t1 * DD;
            }
        } else {
            if (!grouped) {
                size_t q0 = (size_t)p0 * (SS * HH) + seg * HH;
                size_t q1 = (size_t)p1 * (SS * HH) + seg * HH;
                pa0h = gh1s_hi + q0; pa0l = gh1s_lo + q0;
                pa1h = gh1s_hi + q1; pa1l = gh1s_lo + q1;
            } else {
                v0 = p0 < mend; v1 = p1 < mend;
                size_t q0 = (size_t)(v0 ? p0 : 0) * (GG * HH) + seg * HH;
                size_t q1 = (size_t)(v1 ? p1 : 0) * (GG * HH) + seg * HH;
                pa0h = gh1g_hi + q0; pa0l = gh1g_lo + q0;
                pa1h = gh1g_hi + q1; pa1l = gh1g_lo + q1;
            }
        }
    }
    const __half* pb0h = wH + (size_t)r0 * KTOT;
    const __half* pb1h = wH + (size_t)r1 * KTOT;
    const __half* pb0l = wL + (size_t)r0 * KTOT;
    const __half* pb1l = wL + (size_t)r1 * KTOT;

    // stage layout: [Ah 10240][Al 10240][Bh 10240][Bl 10240]
    auto load = [&](int buf, int it) {
        uint32_t sB = base + buf * STAGEB;
        int ke = it * BK + kadd;
        cp16(sB + o0, pa0h + ke, v0);
        cp16(sB + o1, pa1h + ke, v1);
        cp16(sB + ARRB + o0, pa0l + ke, v0);
        cp16(sB + ARRB + o1, pa1l + ke, v1);
        cp16(sB + 2 * ARRB + o0, pb0h + ke, true);
        cp16(sB + 2 * ARRB + o1, pb1h + ke, true);
        cp16(sB + 3 * ARRB + o0, pb0l + ke, true);
        cp16(sB + 3 * ARRB + o1, pb1l + ke, true);
        CPC();
    };

    float d[4][4][4];
#pragma unroll
    for (int i = 0; i < 4; i++)
#pragma unroll
        for (int j = 0; j < 4; j++)
#pragma unroll
            for (int q = 0; q < 4; q++) d[i][j][q] = 0.f;

    const int NIT = KTOT / BK;
    load(0, 0);

    for (int it = 0; it < NIT; it++) {
        const int buf = it & 1;
        if (it + 1 < NIT) { load(buf ^ 1, it + 1); CPW(1); }
        else CPW(0);
        __syncthreads();
        const uint32_t sB = base + buf * STAGEB;

#pragma unroll
        for (int ks = 0; ks < 2; ks++) {
            const uint32_t colb = (uint32_t)((ks * 16 + ((lane >> 4) << 3)) << 1);
            uint32_t ah[4][4], al[4][4], bh[4][2], bl[4][2];
#pragma unroll
            for (int mt = 0; mt < 4; mt++) {
                uint32_t addr = sB + (uint32_t)(wm * 64 + mt * 16 + (lane & 15)) * LDHB + colb;
                LDSM4(ah[mt], addr);
                LDSM4(al[mt], addr + ARRB);
            }
#pragma unroll
            for (int np = 0; np < 2; np++) {
                uint32_t addr = sB + 2 * ARRB
                              + (uint32_t)(wn * 32 + np * 16 + (lane & 15)) * LDHB + colb;
                uint32_t q[4];
                LDSM4(q, addr);
                bh[np * 2][0] = q[0]; bh[np * 2][1] = q[2];
                bh[np * 2 + 1][0] = q[1]; bh[np * 2 + 1][1] = q[3];
                LDSM4(q, addr + ARRB);
                bl[np * 2][0] = q[0]; bl[np * 2][1] = q[2];
                bl[np * 2 + 1][0] = q[1]; bl[np * 2 + 1][1] = q[3];
            }
#pragma unroll
            for (int mt = 0; mt < 4; mt++)
#pragma unroll
                for (int nt = 0; nt < 4; nt++) MMA16(d[mt][nt], ah[mt], bh[nt]);
#pragma unroll
            for (int mt = 0; mt < 4; mt++)
#pragma unroll
                for (int nt = 0; nt < 4; nt++) MMA16(d[mt][nt], ah[mt], bl[nt]);
#pragma unroll
            for (int mt = 0; mt < 4; mt++)
#pragma unroll
                for (int nt = 0; nt < 4; nt++) MMA16(d[mt][nt], al[mt], bh[nt]);
        }
        __syncthreads();
    }

    // ---- epilogue ----
    float bb0[4], bb1[4];
#pragma unroll
    for (int nt = 0; nt < 4; nt++) {
        int cbx = wn * 32 + nt * 8 + 2 * (lane & 3);
        bb0[nt] = bias[bias_off + cbx];
        bb1[nt] = bias[bias_off + cbx + 1];
    }

#pragma unroll
    for (int mt = 0; mt < 4; mt++) {
#pragma unroll
        for (int half = 0; half < 2; half++) {
            int p = m0 + wm * 64 + mt * 16 + (lane >> 2) + half * 8;
            if (grouped && p >= mend) continue;
            if (LAYER == 1) {
                __half *dh, *dl;
                if (!grouped) {
                    size_t o = (size_t)p * (SS * HH) + colstart;
                    dh = gh1s_hi + o; dl = gh1s_lo + o;
                } else {
                    size_t o = (size_t)p * (GG * HH) + colstart;
                    dh = gh1g_hi + o; dl = gh1g_lo + o;
                }
#pragma unroll
                for (int nt = 0; nt < 4; nt++) {
                    int cbx = wn * 32 + nt * 8 + 2 * (lane & 3);
                    float u0 = d[mt][nt][half * 2 + 0] + bb0[nt];
                    float u1 = d[mt][nt][half * 2 + 1] + bb1[nt];
                    u0 = u0 > 0.f ? u0 : 0.f;
                    u1 = u1 > 0.f ? u1 : 0.f;
                    __half h0 = __float2half_rn(u0), h1 = __float2half_rn(u1);
                    __half2 H; H.x = h0; H.y = h1;
                    __half2 L;
                    L.x = __float2half_rn(u0 - __half2float(h0));
                    L.y = __float2half_rn(u1 - __half2float(h1));
                    *reinterpret_cast<__half2*>(dh + cbx) = H;
                    *reinterpret_cast<__half2*>(dl + cbx) = L;
                }
            } else {
                float* dst = (!grouped) ? g_outs + (size_t)p * (SS * DD) + colstart
                                        : g_outg + (size_t)g_perm[p] * (GG * DD) + colstart;
#pragma unroll
                for (int nt = 0; nt < 4; nt++) {
                    int cbx = wn * 32 + nt * 8 + 2 * (lane & 3);
                    float u0 = d[mt][nt][half * 2 + 0] + bb0[nt];
                    float u1 = d[mt][nt][half * 2 + 1] + bb1[nt];
                    *reinterpret_cast<float2*>(dst + cbx) = make_float2(u0, u1);
                }
            }
        }
    }
}

// ---------------- gate + combine (float4 combine) ----------------------------
__global__ void k_gate(const float* __restrict__ x, const float* __restrict__ cond_emb,
                       const float* __restrict__ gate_W, const float* __restrict__ gate_b,
                       float* __restrict__ out) {
    const int n = blockIdx.x;
    const int FD = DD + CC;
    __shared__ float gx[DD + CC], lg[KK * 4], w[KK * 4];
    const int t = threadIdx.x;
    const float* xr = x + (size_t)n * DD;
    for (int i = t; i < DD; i += 128) gx[i] = xr[i];
    if (t < CC) gx[DD + t] = cond_emb[g_gid[n] * CC + t];
    __syncthreads();
    const int warp = t >> 5, lane = t & 31, p0 = warp * 3;
    float s0 = 0.f, s1 = 0.f, s2 = 0.f;
    for (int f = lane; f < FD; f += 32) {
        float xv = gx[f];
        int p;
        p = p0 + 0; s0 = fmaf(xv, gate_W[((p >> 2) * FD + f) * 4 + (p & 3)], s0);
        p = p0 + 1; s1 = fmaf(xv, gate_W[((p >> 2) * FD + f) * 4 + (p & 3)], s1);
        p = p0 + 2; s2 = fmaf(xv, gate_W[((p >> 2) * FD + f) * 4 + (p & 3)], s2);
    }
#pragma unroll
    for (int o = 16; o > 0; o >>= 1) {
        s0 += __shfl_down_sync(0xffffffffu, s0, o);
        s1 += __shfl_down_sync(0xffffffffu, s1, o);
        s2 += __shfl_down_sync(0xffffffffu, s2, o);
    }
    if (lane == 0) {
        lg[p0 + 0] = s0 + gate_b[p0 + 0];
        lg[p0 + 1] = s1 + gate_b[p0 + 1];
        lg[p0 + 2] = s2 + gate_b[p0 + 2];
    }
    __syncthreads();
    if (t < KK) {
        float l0 = lg[t * 4], l1 = lg[t * 4 + 1], l2 = lg[t * 4 + 2], l3 = lg[t * 4 + 3];
        float m = fmaxf(fmaxf(l0, l1), fmaxf(l2, l3));
        float e0 = expf(l0 - m), e1 = expf(l1 - m), e2 = expf(l2 - m), e3 = expf(l3 - m);
        float inv = 1.f / (e0 + e1 + e2 + e3);
        w[t * 4] = e0 * inv; w[t * 4 + 1] = e1 * inv;
        w[t * 4 + 2] = e2 * inv; w[t * 4 + 3] = e3 * inv;
    }
    __syncthreads();
    const float4* so4 = reinterpret_cast<const float4*>(g_outs + (size_t)n * (SS * DD));
    const float4* go4 = reinterpret_cast<const float4*>(g_outg + (size_t)n * (GG * DD));
    // t < 128 covers DD/4 = 128 float4 exactly
    {
        float4 e0 = so4[t], e1 = so4[DD / 4 + t], e2 = go4[t], e3 = go4[DD / 4 + t];
#pragma unroll
        for (int k = 0; k < KK; k++) {
            float w0 = w[k * 4], w1 = w[k * 4 + 1], w2 = w[k * 4 + 2], w3 = w[k * 4 + 3];
            float4 r;
            r.x = w0 * e0.x + w1 * e1.x + w2 * e2.x + w3 * e3.x;
            r.y = w0 * e0.y + w1 * e1.y + w2 * e2.y + w3 * e3.y;
            r.z = w0 * e0.z + w1 * e1.z + w2 * e2.z + w3 * e3.z;
            r.w = w0 * e0.w + w1 * e1.w + w2 * e2.w + w3 * e3.w;
            reinterpret_cast<float4*>(out)[((size_t)k * NTOK + n) * (DD / 4) + t] = r;
        }
    }
}

// ---------------- launch ------------------------------------------------------
extern "C" void kernel_launch(void* const* d_in, const int* in_sizes, int n_in,
                              void* d_out, int out_size) {
    const float* x   = (const float*)d_in[0];
    const int* nti   = (const int*)d_in[1];
    const int* e2g   = (const int*)d_in[2];
    const float* Ws1 = (const float*)d_in[3];
    const float* bs1 = (const float*)d_in[4];
    const float* Ws2 = (const float*)d_in[5];
    const float* bs2 = (const float*)d_in[6];
    const float* Wg1 = (const float*)d_in[7];
    const float* bg1 = (const float*)d_in[8];
    const float* Wg2 = (const float*)d_in[9];
    const float* bg2 = (const float*)d_in[10];
    const float* cemb = (const float*)d_in[11];
    const float* gW  = (const float*)d_in[12];
    const float* gb  = (const float*)d_in[13];
    float* out = (float*)d_out;

    cudaFuncSetAttribute(k_mma<1>, cudaFuncAttributeMaxDynamicSharedMemorySize, SMEM_TOT);
    cudaFuncSetAttribute(k_mma<2>, cudaFuncAttributeMaxDynamicSharedMemorySize, SMEM_TOT);

    k_prep<<<1, 256>>>(nti, e2g);
    k_cvt_x<<<NTOK * DD / 4 / 256, 256>>>((const float4*)x);
    k_cvt_w<1><<<dim3(DD / 64, HH / 64, NBANK), 256>>>(Ws1, Wg1);
    k_cvt_w<2><<<dim3(HH / 64, DD / 64, NBANK), 256>>>(Ws2, Wg2);
    k_mma<1><<<dim3(NSHT + MAXTILES, (SS * HH) / BN), 256, SMEM_TOT>>>(bs1, bg1);
    k_mma<2><<<dim3(NSHT + MAXTILES, (SS * DD) / BN), 256, SMEM_TOT>>>(bs2, bg2);
    k_gate<<<NTOK, 128>>>(x, cemb, gW, gb, out);
}